// round 8
// baseline (speedup 1.0000x reference)
#include <cuda_runtime.h>
#include <cuda_fp16.h>
#include <cstdint>
#include <cstddef>

// ---------------------------------------------------------------------------
// Fused GPTQ 4-bit dequant + fp16 GEMM via mma.sync (HMMA), sm_103 base arch.
//
// R8 change vs R7: eliminate the producer/consumer phase serialization.
//  - B(c+1) dequant+STS is interleaved INTO the MMA loop of chunk c
//  - A is triple-buffered via cp.async (A(c+2) issued during chunk c)
//  - q words double-buffered in registers
//  - ONE __syncthreads per chunk (was two)
// CTA 128 threads (4 warps, 2m x 2n of 64x64), tile 128x128x64, 2 CTAs/SM.
//
//   x      : float32 [4096, 4096]
//   qweight: int32   [512, 11008]  nibble j (shift 4*j) -> k = kp*8 + j
//   qzeros : int32   [1, 1376]     nibble (n%8) -> zero for col n; +1 (GPTQ)
//   scales : float32 [1, 11008]
//   out    : float32 [4096, 11008]
//
// Pre-pass: X f32 -> f16 into g_Xh, K-permuted within each 8-group
// (pairs (t, t+4)) matching ((q >> 4t) & 0x000F000F) | 0x64006400.
// Same permutation on A and B => contraction unchanged.
// ---------------------------------------------------------------------------

static constexpr int M_DIM = 4096;
static constexpr int K_DIM = 4096;
static constexpr int N_DIM = 11008;

static constexpr int BM = 128;
static constexpr int BN = 128;
static constexpr int BK = 64;                    // halves (128 B)
static constexpr int CHUNKS = K_DIM / BK;        // 64
static constexpr int NTHREADS = 128;             // 4 warps

// dynamic smem: A 3x16KB + B 2x16KB = 80 KB (2 CTAs/SM -> 160 KB/SM)
static constexpr uint32_t A_SZ = BM * 128;       // 16384 B per stage
static constexpr uint32_t B_SZ = BN * 128;       // 16384 B per stage
static constexpr uint32_t SMEM_BYTES = 3 * A_SZ + 2 * B_SZ;  // 81920

__device__ __half g_Xh[(size_t)M_DIM * K_DIM];   // 32 MB scratch (static)

// ---------------- helpers ----------------
__device__ __forceinline__ uint32_t h2u(__half2 h) { return *reinterpret_cast<uint32_t*>(&h); }
__device__ __forceinline__ __half2  u2h(uint32_t u) { return *reinterpret_cast<__half2*>(&u); }
__device__ __forceinline__ float    rnd16(float x) { return __half2float(__float2half_rn(x)); }

__device__ __forceinline__ void cp16(uint32_t dst, const void* src) {
    asm volatile("cp.async.cg.shared.global [%0], [%1], 16;" :: "r"(dst), "l"(src));
}
__device__ __forceinline__ void ldsm4(uint32_t* r, uint32_t addr) {
    asm volatile("ldmatrix.sync.aligned.m8n8.x4.shared.b16 {%0,%1,%2,%3}, [%4];"
                 : "=r"(r[0]), "=r"(r[1]), "=r"(r[2]), "=r"(r[3]) : "r"(addr));
}
__device__ __forceinline__ void mma16816(float* c, const uint32_t* a,
                                         uint32_t b0, uint32_t b1) {
    asm volatile("mma.sync.aligned.m16n8k16.row.col.f32.f16.f16.f32 "
                 "{%0,%1,%2,%3}, {%4,%5,%6,%7}, {%8,%9}, {%0,%1,%2,%3};"
                 : "+f"(c[0]), "+f"(c[1]), "+f"(c[2]), "+f"(c[3])
                 : "r"(a[0]), "r"(a[1]), "r"(a[2]), "r"(a[3]), "r"(b0), "r"(b1));
}

// dequant 2 packed rows (pr0, pr0+1) of this thread's column into smem
__device__ __forceinline__ void dq2(uint32_t brow_base, uint32_t bx,
                                    const uint32_t* q, int pr0,
                                    __half2 z2, __half2 s2v) {
#pragma unroll
    for (int pr = pr0; pr < pr0 + 2; ++pr) {
        const uint32_t w = q[pr];
        uint32_t u[4];
#pragma unroll
        for (int t = 0; t < 4; ++t) {
            const uint32_t hb = ((w >> (4 * t)) & 0x000F000Fu) | 0x64006400u;
            u[t] = h2u(__hmul2(__hsub2(u2h(hb), z2), s2v));
        }
        const uint32_t dst = brow_base + (((uint32_t)pr * 16) ^ bx);
        asm volatile("st.shared.v4.b32 [%0], {%1,%2,%3,%4};"
                     :: "r"(dst), "r"(u[0]), "r"(u[1]), "r"(u[2]), "r"(u[3])
                     : "memory");
    }
}

// ---------------------------------------------------------------------------
// Pre-pass: f32 -> f16 with per-8-group K permutation (pairs (t, t+4)).
// ---------------------------------------------------------------------------
__global__ void __launch_bounds__(256)
convert_x(const float* __restrict__ X) {
    const size_t e = (size_t)blockIdx.x * blockDim.x + threadIdx.x;
    if (e >= (size_t)M_DIM * (K_DIM / 8)) return;
    const float4* s = reinterpret_cast<const float4*>(X) + e * 2;
    const float4 lo = s[0];
    const float4 hi = s[1];
    uint4 o;
    o.x = h2u(__floats2half2_rn(lo.x, hi.x));
    o.y = h2u(__floats2half2_rn(lo.y, hi.y));
    o.z = h2u(__floats2half2_rn(lo.z, hi.z));
    o.w = h2u(__floats2half2_rn(lo.w, hi.w));
    reinterpret_cast<uint4*>(g_Xh)[e] = o;
}

// ---------------------------------------------------------------------------
__global__ void __launch_bounds__(NTHREADS, 2)
gemm_mma(const int*   __restrict__ qweight,
         const int*   __restrict__ qzeros,
         const float* __restrict__ scales,
         float*       __restrict__ Y) {
    extern __shared__ char smem[];
    const uint32_t sb = (uint32_t)__cvta_generic_to_shared(smem);
    const uint32_t aStg[3] = {0u, A_SZ, 2 * A_SZ};
    const uint32_t bStg[2] = {3 * A_SZ, 3 * A_SZ + B_SZ};

    const int tid  = threadIdx.x;
    const int warp = tid >> 5;
    const int lane = tid & 31;
    const int wm   = warp >> 1;      // 0..1 (64-row slice)
    const int wn   = warp & 1;       // 0..1 (64-col slice)
    const int bm   = blockIdx.y * BM;
    const int bn   = blockIdx.x * BN;

    // dequant constants: one column per thread, 8 packed rows per chunk
    const int gcol = bn + tid;
    const int zraw = (qzeros[gcol >> 3] >> ((gcol & 7) * 4)) & 0xF;
    const __half2 s2v = __half2half2(__float2half_rn(scales[gcol]));
    const __half2 z2  = __half2half2(__float2half_rn((float)(1025 + zraw)));
    const int* qcol = qweight + gcol;
    const uint32_t bx = (uint32_t)(tid & 7) << 4;   // STS swizzle for this col

    float acc[4][8][4];
#pragma unroll
    for (int i = 0; i < 4; ++i)
#pragma unroll
        for (int j = 0; j < 8; ++j)
#pragma unroll
            for (int t = 0; t < 4; ++t) acc[i][j][t] = 0.0f;

    // A tile loader (8 x 16B per thread)
    auto loadA = [&](int c, int stg) {
        const uint32_t aB = sb + aStg[stg];
        const int k0 = c * BK;
#pragma unroll
        for (int i = 0; i < 8; ++i) {
            const int e = tid + i * NTHREADS;
            const int r = e >> 3, g = e & 7;
            const uint32_t dst = aB +
                (uint32_t)(r * 128 + ((g * 16) ^ ((r & 7) << 4)));
            cp16(dst, g_Xh + (size_t)(bm + r) * K_DIM + k0 + g * 8);
        }
        asm volatile("cp.async.commit_group;" ::: "memory");
    };

    // ---- prologue ----
    loadA(0, 0);
    loadA(1, 1);
    uint32_t q[8];
#pragma unroll
    for (int pr = 0; pr < 8; ++pr)
        q[pr] = (uint32_t)qcol[(size_t)pr * N_DIM];
    // dequant B(0) into bStg[0]
    {
        const uint32_t brow = sb + bStg[0] + (uint32_t)tid * 128;
#pragma unroll
        for (int pr0 = 0; pr0 < 8; pr0 += 2) dq2(brow, bx, q, pr0, z2, s2v);
    }
#pragma unroll
    for (int pr = 0; pr < 8; ++pr)
        q[pr] = (uint32_t)qcol[(size_t)(8 + pr) * N_DIM];
    asm volatile("cp.async.wait_group 1;" ::: "memory");   // A(0) ready
    __syncthreads();

    for (int c = 0; c < CHUNKS; ++c) {
        const int buf = c & 1;
        const uint32_t aB = sb + aStg[c % 3];
        const uint32_t bB = sb + bStg[buf];
        const uint32_t bW = sb + bStg[buf ^ 1] + (uint32_t)tid * 128;

        if (c + 2 < CHUNKS) loadA(c + 2, (c + 2) % 3);

        uint32_t qn[8];
        if (c + 2 < CHUNKS) {
#pragma unroll
            for (int pr = 0; pr < 8; ++pr)
                qn[pr] = (uint32_t)qcol[(size_t)((c + 2) * 8 + pr) * N_DIM];
        }

        // ---- MMA over chunk c, interleaved with dequant of B(c+1) ----
#pragma unroll
        for (int kk = 0; kk < 4; ++kk) {
            const uint32_t kb = kk * 32;
            uint32_t a[4][4], b[4][4];
#pragma unroll
            for (int j = 0; j < 4; ++j) {
                const int row = wn * 64 + j * 16 + ((lane >> 4) << 3) + (lane & 7);
                const uint32_t addr = bB + row * 128 +
                    ((kb + (((lane >> 3) & 1) << 4)) ^ ((row & 7) << 4));
                ldsm4(b[j], addr);
            }
#pragma unroll
            for (int i = 0; i < 4; ++i) {
                const int row = wm * 64 + i * 16 + (lane & 15);
                const uint32_t addr = aB + row * 128 +
                    ((kb + ((lane >> 4) << 4)) ^ ((row & 7) << 4));
                ldsm4(a[i], addr);
            }
            // dequant 2 rows of B(c+1) between LDSM and MMA block
            if (c + 1 < CHUNKS) dq2(bW, bx, q, kk * 2, z2, s2v);
#pragma unroll
            for (int i = 0; i < 4; ++i)
#pragma unroll
                for (int j = 0; j < 4; ++j) {
                    mma16816(acc[i][2 * j],     a[i], b[j][0], b[j][1]);
                    mma16816(acc[i][2 * j + 1], a[i], b[j][2], b[j][3]);
                }
        }

        if (c + 2 < CHUNKS) {
#pragma unroll
            for (int pr = 0; pr < 8; ++pr) q[pr] = qn[pr];
            asm volatile("cp.async.wait_group 1;" ::: "memory");  // A(c+1)
        } else {
            asm volatile("cp.async.wait_group 0;" ::: "memory");
        }
        __syncthreads();   // B(c+1) STS visible; all reads of stage done
    }

    // ---- epilogue: round via fp16, store f32 ----
#pragma unroll
    for (int i = 0; i < 4; ++i) {
        const int m0 = bm + wm * 64 + i * 16 + (lane >> 2);
        float* y0 = Y + (size_t)m0 * N_DIM;
        float* y1 = y0 + (size_t)8 * N_DIM;
#pragma unroll
        for (int jj = 0; jj < 8; ++jj) {
            const int n0 = bn + wn * 64 + jj * 8 + 2 * (lane & 3);
            float2 v0, v1;
            v0.x = rnd16(acc[i][jj][0]);
            v0.y = rnd16(acc[i][jj][1]);
            v1.x = rnd16(acc[i][jj][2]);
            v1.y = rnd16(acc[i][jj][3]);
            *reinterpret_cast<float2*>(y0 + n0) = v0;
            *reinterpret_cast<float2*>(y1 + n0) = v1;
        }
    }
}

// ---------------------------------------------------------------------------
extern "C" void kernel_launch(void* const* d_in, const int* in_sizes, int n_in,
                              void* d_out, int out_size) {
    const float* x       = (const float*)d_in[0];
    const int*   qweight = (const int*)d_in[1];
    const int*   qzeros  = (const int*)d_in[2];
    const float* scales  = (const float*)d_in[3];
    float*       out     = (float*)d_out;

    cudaFuncSetAttribute(gemm_mma,
                         cudaFuncAttributeMaxDynamicSharedMemorySize, SMEM_BYTES);

    const int groups = M_DIM * (K_DIM / 8);
    convert_x<<<(groups + 255) / 256, 256>>>(x);

    dim3 grid(N_DIM / BN, M_DIM / BM);   // 86 x 32
    gemm_mma<<<grid, NTHREADS, SMEM_BYTES>>>(qweight, qzeros, scales, out);
}

// round 9
// speedup vs baseline: 1.1375x; 1.1375x over previous
#include <cuda_runtime.h>
#include <cuda_fp16.h>
#include <cstdint>
#include <cstddef>

// ---------------------------------------------------------------------------
// Fused GPTQ 4-bit dequant + fp16 GEMM via mma.sync (HMMA), sm_103 base arch.
//
// R9 vs R6 (best=950us): remove scale/zero from the hot loop algebraically.
//   B smem holds EXACT fp16 integers (1024 + q)  [2 ALU ops per half2]
//   out[m,n] = s[n] * ( acc[m,n] - (1025 + z[n]) * R[m] ),
//   acc = sum_k x_hat*(1024+q),  R[m] = sum_k x_hat[m,k]  (pre-pass).
// Skeleton unchanged: CTA 128x128x64, 256 thr, 8 warps (2m x 4n of 64x32),
// double-buffered cp.async A, 2 CTAs/SM.
//
//   x      : float32 [4096, 4096]
//   qweight: int32   [512, 11008]  nibble j (shift 4*j) -> k = kp*8 + j
//   qzeros : int32   [1, 1376]     nibble (n%8) -> zero for col n; +1 (GPTQ)
//   scales : float32 [1, 11008]
//   out    : float32 [4096, 11008]
//
// Pre-pass 1: X f32 -> f16 into g_Xh, K-permuted within each 8-group
// (pairs (t, t+4)) matching ((q >> 4t) & 0x000F000F) | 0x64006400.
// Pre-pass 2: R[m] = sum of fp16(x) per row (fp32, warp-per-row).
// ---------------------------------------------------------------------------

static constexpr int M_DIM = 4096;
static constexpr int K_DIM = 4096;
static constexpr int N_DIM = 11008;

static constexpr int BM = 128;
static constexpr int BN = 128;
static constexpr int BK = 64;                    // halves (128 B)
static constexpr int CHUNKS = K_DIM / BK;        // 64

// dynamic smem: A 2x16KB, B 2x16KB = 64 KB (2 CTAs/SM -> 128 KB/SM)
static constexpr uint32_t A_SZ = BM * 128;
static constexpr uint32_t B_SZ = BN * 128;
static constexpr uint32_t SMEM_BYTES = 2 * A_SZ + 2 * B_SZ;  // 65536

__device__ __half g_Xh[(size_t)M_DIM * K_DIM];   // 32 MB scratch (static)
__device__ float  g_R[M_DIM];                    // row sums of fp16(x)

// ---------------- helpers ----------------
__device__ __forceinline__ uint32_t h2u(__half2 h) { return *reinterpret_cast<uint32_t*>(&h); }
__device__ __forceinline__ float    rnd16(float x) { return __half2float(__float2half_rn(x)); }

__device__ __forceinline__ void cp16(uint32_t dst, const void* src) {
    asm volatile("cp.async.cg.shared.global [%0], [%1], 16;" :: "r"(dst), "l"(src));
}
__device__ __forceinline__ void ldsm4(uint32_t* r, uint32_t addr) {
    asm volatile("ldmatrix.sync.aligned.m8n8.x4.shared.b16 {%0,%1,%2,%3}, [%4];"
                 : "=r"(r[0]), "=r"(r[1]), "=r"(r[2]), "=r"(r[3]) : "r"(addr));
}
__device__ __forceinline__ void mma16816(float* c, const uint32_t* a,
                                         uint32_t b0, uint32_t b1) {
    asm volatile("mma.sync.aligned.m16n8k16.row.col.f32.f16.f16.f32 "
                 "{%0,%1,%2,%3}, {%4,%5,%6,%7}, {%8,%9}, {%0,%1,%2,%3};"
                 : "+f"(c[0]), "+f"(c[1]), "+f"(c[2]), "+f"(c[3])
                 : "r"(a[0]), "r"(a[1]), "r"(a[2]), "r"(a[3]), "r"(b0), "r"(b1));
}

// ---------------------------------------------------------------------------
// Pre-pass 1: f32 -> f16 with per-8-group K permutation (pairs (t, t+4)).
// ---------------------------------------------------------------------------
__global__ void __launch_bounds__(256)
convert_x(const float* __restrict__ X) {
    const size_t e = (size_t)blockIdx.x * blockDim.x + threadIdx.x;
    if (e >= (size_t)M_DIM * (K_DIM / 8)) return;
    const float4* s = reinterpret_cast<const float4*>(X) + e * 2;
    const float4 lo = s[0];
    const float4 hi = s[1];
    uint4 o;
    o.x = h2u(__floats2half2_rn(lo.x, hi.x));
    o.y = h2u(__floats2half2_rn(lo.y, hi.y));
    o.z = h2u(__floats2half2_rn(lo.z, hi.z));
    o.w = h2u(__floats2half2_rn(lo.w, hi.w));
    reinterpret_cast<uint4*>(g_Xh)[e] = o;
}

// ---------------------------------------------------------------------------
// Pre-pass 2: R[m] = sum_k fp16(x[m,k])  (fp32, lane partials + shfl reduce)
// ---------------------------------------------------------------------------
__global__ void __launch_bounds__(256)
rowsum_x() {
    const int row  = blockIdx.x * 8 + (threadIdx.x >> 5);
    const int lane = threadIdx.x & 31;
    const uint4* p = reinterpret_cast<const uint4*>(g_Xh + (size_t)row * K_DIM);
    float s = 0.0f;
#pragma unroll
    for (int i = 0; i < 16; ++i) {               // 16*32*8 = 4096 halves
        const uint4 v = p[lane + i * 32];
        const uint32_t w[4] = {v.x, v.y, v.z, v.w};
#pragma unroll
        for (int j = 0; j < 4; ++j) {
            const float2 f = __half22float2(*reinterpret_cast<const __half2*>(&w[j]));
            s += f.x + f.y;
        }
    }
#pragma unroll
    for (int o = 16; o; o >>= 1) s += __shfl_xor_sync(0xFFFFFFFFu, s, o);
    if (lane == 0) g_R[row] = s;
}

// ---------------------------------------------------------------------------
__global__ void __launch_bounds__(256, 2)
gemm_mma(const int*   __restrict__ qweight,
         const int*   __restrict__ qzeros,
         const float* __restrict__ scales,
         float*       __restrict__ Y) {
    extern __shared__ char smem[];
    const uint32_t sb = (uint32_t)__cvta_generic_to_shared(smem);
    const uint32_t aOff[2] = {0u, A_SZ};
    const uint32_t bOff[2] = {2 * A_SZ, 2 * A_SZ + B_SZ};

    const int tid  = threadIdx.x;
    const int warp = tid >> 5;
    const int lane = tid & 31;
    const int wm   = warp >> 2;      // 0..1  (64-row slice)
    const int wn   = warp & 3;       // 0..3  (32-col slice)
    const int bm   = blockIdx.y * BM;
    const int bn   = blockIdx.x * BN;

    // dequant mapping: 2 threads per column, 4 packed rows each
    const int nloc = tid & 127;                  // column 0..127
    const int half = tid >> 7;                   // 0: pr 0-3, 1: pr 4-7
    const int gcol = bn + nloc;
    const int* qcol = qweight + (size_t)half * 4 * N_DIM + gcol;

    float acc[4][4][4];
#pragma unroll
    for (int i = 0; i < 4; ++i)
#pragma unroll
        for (int j = 0; j < 4; ++j)
#pragma unroll
            for (int t = 0; t < 4; ++t) acc[i][j][t] = 0.0f;

    // ---- prologue: A chunk 0 + q chunk 0 ----
#pragma unroll
    for (int i = 0; i < 4; ++i) {
        const int e = tid + i * 256;
        const int r = e >> 3, g = e & 7;
        const uint32_t dst = sb + aOff[0] +
            (uint32_t)(r * 128 + ((g * 16) ^ ((r & 7) << 4)));
        cp16(dst, g_Xh + (size_t)(bm + r) * K_DIM + g * 8);
    }
    asm volatile("cp.async.commit_group;" ::: "memory");
    uint32_t q[4];
#pragma unroll
    for (int pr = 0; pr < 4; ++pr)
        q[pr] = (uint32_t)qcol[(size_t)pr * N_DIM];

    for (int c = 0; c < CHUNKS; ++c) {
        const int buf = c & 1;

        // ---- B(c): raw nibbles -> exact fp16 (1024+q), 2 ops per half2 ----
        {
            const uint32_t bB   = sb + bOff[buf];
            const uint32_t brow = (uint32_t)nloc * 128;
            const uint32_t bx   = (uint32_t)(nloc & 7) << 4;
#pragma unroll
            for (int pr = 0; pr < 4; ++pr) {
                const uint32_t w = q[pr];
                uint32_t u[4];
#pragma unroll
                for (int t = 0; t < 4; ++t)
                    u[t] = ((w >> (4 * t)) & 0x000F000Fu) | 0x64006400u;
                const uint32_t dst = bB + brow +
                    ((((uint32_t)(half * 4 + pr)) * 16) ^ bx);
                asm volatile("st.shared.v4.b32 [%0], {%1,%2,%3,%4};"
                             :: "r"(dst), "r"(u[0]), "r"(u[1]), "r"(u[2]), "r"(u[3])
                             : "memory");
            }
        }

        // ---- prefetch chunk c+1 (A via cp.async, q via LDG) ----
        if (c + 1 < CHUNKS) {
            const uint32_t aB = sb + aOff[buf ^ 1];
            const int k0 = (c + 1) * BK;
#pragma unroll
            for (int i = 0; i < 4; ++i) {
                const int e = tid + i * 256;
                const int r = e >> 3, g = e & 7;
                const uint32_t dst = aB +
                    (uint32_t)(r * 128 + ((g * 16) ^ ((r & 7) << 4)));
                cp16(dst, g_Xh + (size_t)(bm + r) * K_DIM + k0 + g * 8);
            }
            asm volatile("cp.async.commit_group;" ::: "memory");
#pragma unroll
            for (int pr = 0; pr < 4; ++pr)
                q[pr] = (uint32_t)qcol[(size_t)((c + 1) * 8 + pr) * N_DIM];
            asm volatile("cp.async.wait_group 1;" ::: "memory");
        } else {
            asm volatile("cp.async.wait_group 0;" ::: "memory");
        }
        __syncthreads();   // A(c) + B(c) visible

        // ---- MMA over stage buf: warp tile 64(m) x 32(n) ----
        const uint32_t aB = sb + aOff[buf];
        const uint32_t bB = sb + bOff[buf];
#pragma unroll
        for (int kk = 0; kk < 4; ++kk) {
            const uint32_t kb = kk * 32;
            uint32_t a[4][4], b[2][4];
#pragma unroll
            for (int j = 0; j < 2; ++j) {
                const int row = wn * 32 + j * 16 + ((lane >> 4) << 3) + (lane & 7);
                const uint32_t addr = bB + row * 128 +
                    ((kb + (((lane >> 3) & 1) << 4)) ^ ((row & 7) << 4));
                ldsm4(b[j], addr);
            }
#pragma unroll
            for (int i = 0; i < 4; ++i) {
                const int row = wm * 64 + i * 16 + (lane & 15);
                const uint32_t addr = aB + row * 128 +
                    ((kb + ((lane >> 4) << 4)) ^ ((row & 7) << 4));
                ldsm4(a[i], addr);
            }
#pragma unroll
            for (int i = 0; i < 4; ++i)
#pragma unroll
                for (int j = 0; j < 2; ++j) {
                    mma16816(acc[i][2 * j],     a[i], b[j][0], b[j][1]);
                    mma16816(acc[i][2 * j + 1], a[i], b[j][2], b[j][3]);
                }
        }
        __syncthreads();   // all reads of stage buf done before reuse
    }

    // ---- epilogue: out = rnd16( s[n] * (acc - (1025+z[n]) * R[m]) ) ----
    // per-jj column constants (n0 even; both nibbles in one qzeros word)
    float s0f[4], s1f[4], C0[4], C1[4];
#pragma unroll
    for (int jj = 0; jj < 4; ++jj) {
        const int n0 = bn + wn * 32 + jj * 8 + 2 * (lane & 3);
        const float2 sv = *reinterpret_cast<const float2*>(scales + n0);
        s0f[jj] = sv.x;
        s1f[jj] = sv.y;
        const int qz = qzeros[n0 >> 3];
        const int sh = (n0 & 7) * 4;
        C0[jj] = (float)(1025 + ((qz >> sh) & 0xF));
        C1[jj] = (float)(1025 + ((qz >> (sh + 4)) & 0xF));
    }
#pragma unroll
    for (int i = 0; i < 4; ++i) {
        const int m0 = bm + wm * 64 + i * 16 + (lane >> 2);
        const float R0 = g_R[m0];
        const float R1 = g_R[m0 + 8];
        float* y0 = Y + (size_t)m0 * N_DIM;
        float* y1 = y0 + (size_t)8 * N_DIM;
#pragma unroll
        for (int jj = 0; jj < 4; ++jj) {
            const int n0 = bn + wn * 32 + jj * 8 + 2 * (lane & 3);
            float2 v0, v1;
            v0.x = rnd16(s0f[jj] * (acc[i][jj][0] - C0[jj] * R0));
            v0.y = rnd16(s1f[jj] * (acc[i][jj][1] - C1[jj] * R0));
            v1.x = rnd16(s0f[jj] * (acc[i][jj][2] - C0[jj] * R1));
            v1.y = rnd16(s1f[jj] * (acc[i][jj][3] - C1[jj] * R1));
            *reinterpret_cast<float2*>(y0 + n0) = v0;
            *reinterpret_cast<float2*>(y1 + n0) = v1;
        }
    }
}

// ---------------------------------------------------------------------------
extern "C" void kernel_launch(void* const* d_in, const int* in_sizes, int n_in,
                              void* d_out, int out_size) {
    const float* x       = (const float*)d_in[0];
    const int*   qweight = (const int*)d_in[1];
    const int*   qzeros  = (const int*)d_in[2];
    const float* scales  = (const float*)d_in[3];
    float*       out     = (float*)d_out;

    cudaFuncSetAttribute(gemm_mma,
                         cudaFuncAttributeMaxDynamicSharedMemorySize, SMEM_BYTES);

    const int groups = M_DIM * (K_DIM / 8);
    convert_x<<<(groups + 255) / 256, 256>>>(x);
    rowsum_x<<<M_DIM / 8, 256>>>();

    dim3 grid(N_DIM / BN, M_DIM / BM);   // 86 x 32
    gemm_mma<<<grid, 256, SMEM_BYTES>>>(qweight, qzeros, scales, out);
}